// round 12
// baseline (speedup 1.0000x reference)
#include <cuda_runtime.h>
#include <math.h>

// ---------------------------------------------------------------------------
// MLP 2 -> 64 -> 64 -> 64 -> 1 with chaotic activation.
//   Reference act: x = cos(z)*0.5+0.5; x = R x (1-x) twice.
//   Identity: x(1-x) = sin^2(z)/4  =>  act(z) = v*(R^2/4 - (R^3/16) v),
//   v = sin^2(z), pi-periodic. v via packed mod-pi reduction + MUFU.SIN.
// 1 point per thread (PPT=1): halves smem h-buffer vs PPT=2 -> 3 blocks/SM
// (12 warps, 3/SMSP) to hide the act/LDS latency chains that bound Round 8.
// Weights in smem (broadcast LDS.128 of packed f32x2 pairs); h register-
// resident per layer, handed off through per-thread smem columns (no syncs).
// Inner products use fma.rn.f32x2 (SASS FFMA2) for 2x fp32 throughput.
// ---------------------------------------------------------------------------

#define R_D 3.82843

typedef unsigned long long u64;

__device__ __forceinline__ u64 f2fma(u64 a, u64 b, u64 c) {
    u64 d; asm("fma.rn.f32x2 %0, %1, %2, %3;" : "=l"(d) : "l"(a), "l"(b), "l"(c)); return d;
}
__device__ __forceinline__ u64 f2mul(u64 a, u64 b) {
    u64 d; asm("mul.rn.f32x2 %0, %1, %2;" : "=l"(d) : "l"(a), "l"(b)); return d;
}
__device__ __forceinline__ u64 f2add(u64 a, u64 b) {
    u64 d; asm("add.rn.f32x2 %0, %1, %2;" : "=l"(d) : "l"(a), "l"(b)); return d;
}
__device__ __forceinline__ u64 pk2(float lo, float hi) {
    u64 r; asm("mov.b64 %0, {%1, %2};" : "=l"(r) : "f"(lo), "f"(hi)); return r;
}
__device__ __forceinline__ void upk2(u64 v, float& lo, float& hi) {
    asm("mov.b64 {%0, %1}, %2;" : "=f"(lo), "=f"(hi) : "l"(v));
}

// Activation coefficients
#define ACT_C0 ((float)(R_D * R_D / 4.0))            //  R^2/4
#define ACT_C1 ((float)(-(R_D * R_D * R_D) / 16.0))  // -R^3/16
// mod-pi reduction constants
#define INV_PI   0.3183098861837907f
#define RMAGIC   12582912.0f                         // 1.5 * 2^23
#define PI_HI    3.14159202575683593750f             // 24-bit-safe split of pi
#define PI_MID   6.278329573009626e-7f

// Scalar activation (final layer)
__device__ __forceinline__ float act1(float z) {
    float big = fmaf(z, INV_PI, RMAGIC);
    float n   = big - RMAGIC;                        // round(z/pi)
    float r   = fmaf(n, -PI_HI, z);
    r = fmaf(n, -PI_MID, r);
    float s = __sinf(r);                             // MUFU.SIN, |r| <= pi/2
    float v = s * s;                                 // sin^2(z)
    return v * fmaf(v, ACT_C1, ACT_C0);
}

// Packed activation for a pair of pre-activations
__device__ __forceinline__ u64 act2(float z0, float z1) {
    u64 z   = pk2(z0, z1);
    u64 big = f2fma(z, pk2(INV_PI, INV_PI), pk2(RMAGIC, RMAGIC));
    u64 n   = f2add(big, pk2(-RMAGIC, -RMAGIC));
    u64 r   = f2fma(n, pk2(-PI_HI, -PI_HI), z);
    r = f2fma(n, pk2(-PI_MID, -PI_MID), r);
    float r0, r1; upk2(r, r0, r1);
    float s0 = __sinf(r0);
    float s1 = __sinf(r1);
    u64 s = pk2(s0, s1);
    u64 v = f2mul(s, s);
    return f2mul(v, f2fma(v, pk2(ACT_C1, ACT_C1), pk2(ACT_C0, ACT_C0)));
}

// ---------------------------------------------------------------------------

constexpr int TPB = 128;

// Shared-memory layout (float indices)
constexpr int SM_W2 = 0;               // 64x64
constexpr int SM_W3 = 4096;            // 64x64
constexpr int SM_W1 = 8192;            // 64x2
constexpr int SM_W4 = 8320;            // 1x64
constexpr int SM_B1 = 8384;
constexpr int SM_B2 = 8448;
constexpr int SM_B3 = 8512;
constexpr int SM_B4 = 8576;            // 1
constexpr int SM_HB = 8592;            // byte offset 34368 (16B aligned)
// h buffer: 32 pairs * TPB columns of u64 = 32 KB
constexpr size_t SMEM_BYTES = (size_t)SM_HB * 4 + (size_t)32 * TPB * 8; // 67136 B

// One 64->64 hidden layer, in place (reads fully hoisted to regs first).
__device__ __forceinline__ void hidden_layer1(const float* __restrict__ sm,
                                              int wOff, int bOff,
                                              u64* __restrict__ hb, int tid) {
    u64 h[32];
#pragma unroll
    for (int p = 0; p < 32; p++) h[p] = hb[p * TPB + tid];

    const float* W = sm + wOff;
#pragma unroll 2
    for (int j = 0; j < 64; j += 2) {
        const ulonglong2* w0 = (const ulonglong2*)(W + j * 64);
        const ulonglong2* w1 = (const ulonglong2*)(W + (j + 1) * 64);
        float b0 = sm[bOff + j], b1 = sm[bOff + j + 1];
        // bias folded into one accumulator lane of each chain
        u64 a0 = pk2(b0, 0.0f), a1 = 0ull, a2 = pk2(b1, 0.0f), a3 = 0ull;
#pragma unroll
        for (int q = 0; q < 16; q++) {
            ulonglong2 wa = w0[q];              // broadcast LDS.128
            ulonglong2 wb = w1[q];
            a0 = f2fma(wa.x, h[2 * q],     a0);
            a1 = f2fma(wa.y, h[2 * q + 1], a1);
            a2 = f2fma(wb.x, h[2 * q],     a2);
            a3 = f2fma(wb.y, h[2 * q + 1], a3);
        }
        float l, hh;
        u64 s;
        s = f2add(a0, a1); upk2(s, l, hh); float z0 = l + hh;
        s = f2add(a2, a3); upk2(s, l, hh); float z1 = l + hh;
        hb[(j >> 1) * TPB + tid] = act2(z0, z1);
    }
}

__global__ void __launch_bounds__(TPB)
mlp_kernel(const float* __restrict__ X,
           const float* __restrict__ W1, const float* __restrict__ B1,
           const float* __restrict__ W2, const float* __restrict__ B2,
           const float* __restrict__ W3, const float* __restrict__ B3,
           const float* __restrict__ W4, const float* __restrict__ B4,
           float* __restrict__ O, int N) {
    extern __shared__ float sm[];
    const int tid = threadIdx.x;

    // Cooperative weight staging (vectorized)
    {
        const float4* s4 = (const float4*)W2;
        float4*       t4 = (float4*)(sm + SM_W2);
        for (int i = tid; i < 1024; i += TPB) t4[i] = s4[i];
        s4 = (const float4*)W3;
        t4 = (float4*)(sm + SM_W3);
        for (int i = tid; i < 1024; i += TPB) t4[i] = s4[i];
    }
    if (tid < 128) sm[SM_W1 + tid] = W1[tid];
    if (tid < 64) {
        sm[SM_W4 + tid] = W4[tid];
        sm[SM_B1 + tid] = B1[tid];
        sm[SM_B2 + tid] = B2[tid];
        sm[SM_B3 + tid] = B3[tid];
    }
    if (tid == 0) sm[SM_B4] = B4[0];
    __syncthreads();

    u64* hb = (u64*)(sm + SM_HB);           // 32 * TPB u64, per-thread columns

    const int gid = blockIdx.x * TPB + tid;
    float x0 = 0.0f, x1 = 0.0f;
    if (gid < N) { float2 v = ((const float2*)X)[gid]; x0 = v.x; x1 = v.y; }

    // Layer 1: 2 -> 64
#pragma unroll 4
    for (int j = 0; j < 64; j += 2) {
        float z0 = fmaf(sm[SM_W1 + 2 * j],     x0, fmaf(sm[SM_W1 + 2 * j + 1], x1, sm[SM_B1 + j]));
        float z1 = fmaf(sm[SM_W1 + 2 * j + 2], x0, fmaf(sm[SM_W1 + 2 * j + 3], x1, sm[SM_B1 + j + 1]));
        hb[(j >> 1) * TPB + tid] = act2(z0, z1);
    }

    // Layers 2 & 3: 64 -> 64, in place (per-thread columns, no syncs needed)
    hidden_layer1(sm, SM_W2, SM_B2, hb, tid);
    hidden_layer1(sm, SM_W3, SM_B3, hb, tid);

    // Layer 4: 64 -> 1
    {
        u64 h[32];
#pragma unroll
        for (int p = 0; p < 32; p++) h[p] = hb[p * TPB + tid];
        const ulonglong2* w = (const ulonglong2*)(sm + SM_W4);
        float b4 = sm[SM_B4];
        u64 a0 = pk2(b4, 0.0f), a1 = 0ull, a2 = 0ull, a3 = 0ull;
#pragma unroll
        for (int q = 0; q < 16; q += 2) {
            ulonglong2 wa = w[q];
            ulonglong2 wb = w[q + 1];
            a0 = f2fma(wa.x, h[2 * q],     a0);
            a1 = f2fma(wa.y, h[2 * q + 1], a1);
            a2 = f2fma(wb.x, h[2 * q + 2], a2);
            a3 = f2fma(wb.y, h[2 * q + 3], a3);
        }
        u64 s = f2add(f2add(a0, a1), f2add(a2, a3));
        float l, hh; upk2(s, l, hh);
        float z = l + hh;
        if (gid < N) O[gid] = act1(z);
    }
}

// ---------------------------------------------------------------------------

extern "C" void kernel_launch(void* const* d_in, const int* in_sizes, int n_in,
                              void* d_out, int out_size) {
    const float* X  = (const float*)d_in[0];
    const float* W1 = (const float*)d_in[1];
    const float* B1 = (const float*)d_in[2];
    const float* W2 = (const float*)d_in[3];
    const float* B2 = (const float*)d_in[4];
    const float* W3 = (const float*)d_in[5];
    const float* B3 = (const float*)d_in[6];
    const float* W4 = (const float*)d_in[7];
    const float* B4 = (const float*)d_in[8];
    float* O = (float*)d_out;

    const int N = in_sizes[0] / 2;

    // Opt-in to >48KB dynamic shared memory (host-side, idempotent, capture-safe)
    (void)cudaFuncSetAttribute(mlp_kernel,
                               cudaFuncAttributeMaxDynamicSharedMemorySize,
                               (int)SMEM_BYTES);

    const int blocks = (N + TPB - 1) / TPB;
    mlp_kernel<<<blocks, TPB, SMEM_BYTES>>>(X, W1, B1, W2, B2, W3, B3, W4, B4, O, N);
}